// round 1
// baseline (speedup 1.0000x reference)
#include <cuda_runtime.h>
#include <math.h>

// Problem constants (fixed by setup_inputs)
#define N_TOT 5000
#define NE    4000
#define NI    1000
#define T_STEPS 1000
#define NBLK  40
#define NTHR  128
#define NWARP (NTHR/32)
#define CAP   128   // max fired per block = block size

// Model constants, matching the python reference (f32 roundings)
#define GLE 0.08f
#define GLI 0.1f
#define GP0 0.004069f
#define GP1 0.02672f
#define GP2 0.003276f
#define GP3 0.02138f
#define C0F ((float)(2.0/7.0))
#define C1F ((float)(117.0/7.0))
#define C2F ((float)(-23.0/7.0))
#define PIF 3.14159274101257324f   // float32(pi)

// ------- static device scratch (no allocations allowed) -------
__device__ float g_connT[(size_t)N_TOT * N_TOT];   // 100 MB: conn transposed
__device__ int   g_list[2][NBLK * CAP];            // double-buffered fired lists (segmented per block)
__device__ int   g_cntE[2][NBLK];
__device__ int   g_cntT[2][NBLK];
__device__ float g_outPart[NBLK * T_STEPS];        // per-block partial sums of g*W
__device__ unsigned g_barCnt;
__device__ volatile unsigned g_barGen;

// ---------------- transpose conn -> connT ----------------
__global__ void snn_transpose(const float* __restrict__ conn) {
    __shared__ float tile[32][33];
    int bx = blockIdx.x * 32, by = blockIdx.y * 32;
    int x = bx + threadIdx.x;
    #pragma unroll
    for (int r = threadIdx.y; r < 32; r += 8) {
        int y = by + r;
        if (x < N_TOT && y < N_TOT)
            tile[r][threadIdx.x] = conn[(size_t)y * N_TOT + x];
    }
    __syncthreads();
    int xo = by + threadIdx.x;
    #pragma unroll
    for (int r = threadIdx.y; r < 32; r += 8) {
        int yo = bx + r;
        if (xo < N_TOT && yo < N_TOT)
            g_connT[(size_t)yo * N_TOT + xo] = tile[threadIdx.x][r];  // connT[j][i] = conn[i][j]
    }
}

// ---------------- init: reset scratch + column 0 of outputs ----------------
__global__ void snn_init(float* Vout, float* gout, float* spkout) {
    int i = blockIdx.x * blockDim.x + threadIdx.x;
    if (i == 0) { g_barCnt = 0; g_barGen = 0; }
    if (i < 2 * NBLK) {
        ((int*)g_cntE)[i] = 0;
        ((int*)g_cntT)[i] = 0;
    }
    if (i < N_TOT) {
        size_t o = (size_t)i * T_STEPS;
        Vout[o]   = -58.5f;  // theta2V(0)
        gout[o]   = 0.0f;
        spkout[o] = 0.0f;
    }
}

// ---------------- main persistent simulation kernel ----------------
__global__ void __launch_bounds__(NTHR, 1) snn_main(
    const float* __restrict__ dtp,
    const float* __restrict__ Input,   // [N, T] row-major
    const float* __restrict__ Wout,    // [N]
    float* __restrict__ Vout,          // [N, T]
    float* __restrict__ gout,          // [N, T]
    float* __restrict__ spkout)        // [N, T]
{
    const int tid  = threadIdx.x;
    const int b    = blockIdx.x;
    const int i    = b * NTHR + tid;
    const bool active = (i < N_TOT);
    const bool isE    = (i < NE);
    const int  ii     = active ? i : 0;     // clamp for safe gather addressing
    const int  lane   = tid & 31;
    const int  w32    = tid >> 5;

    const float dt   = *dtp;
    const float tauE = 2.0f;
    const float tauI = 5.0f;

    float ga = 0.0f, gb = 0.0f, gs = 0.0f, phase = 0.0f;
    const float wv = active ? Wout[i] : 0.0f;
    const float* inrow = Input + (size_t)ii * T_STEPS;

    __shared__ int   sCntE[NBLK];
    __shared__ int   sCntT[NBLK];
    __shared__ int   sWcnt[NWARP];
    __shared__ float sRed[NWARP];

    for (int t = 1; t < T_STEPS; t++) {
        const int q    = (t - 1) & 1;   // read buffer (spikes from step t-1)
        const int pnew = t & 1;         // write buffer (spikes from step t)

        if (tid < NBLK) {
            sCntE[tid] = g_cntE[q][tid];
            sCntT[tid] = g_cntT[q][tid];
        }
        __syncthreads();

        // -------- sparse gather: m_E(i) and m_I(i) over fired sources --------
        float sumE = 0.0f, sumI = 0.0f;
        #pragma unroll 1
        for (int bb = 0; bb < NBLK; bb++) {
            int cT = sCntT[bb];
            if (cT == 0) continue;
            int cE = sCntE[bb];
            const int* lst = &g_list[q][bb * CAP];
            #pragma unroll 4
            for (int k = 0; k < cT; k++) {
                int j = lst[k];                       // broadcast load
                float v = g_connT[(size_t)j * N_TOT + ii];  // coalesced across lanes
                if (k < cE) sumE += v; else sumI += v;
            }
        }

        // -------- pointwise neuron update (mirrors reference expressions) ----
        float inp = inrow[t];
        float c = cosf(phase);
        float s = sinf(phase);
        float one_c = 1.0f + c;
        float ph2;
        if (isE) {
            ga = ga + (-ga / tauE + GP0 * sumE) * dt;
            gb = gb + (-gb / tauE + GP1 * sumI) * dt;
            gs = gs + (-gs / tauE + GP0 * sumE + GP1 * sumI) * dt;
            ph2 = phase + (-GLE * c + C0F * one_c * inp
                           + ga * (C1F * one_c - s) + gb * (C2F * one_c - s)) * dt;
        } else {
            ga = ga + (-ga / tauI + GP2 * sumE) * dt;
            gb = gb + (-gb / tauI + GP3 * sumI) * dt;
            gs = gs + (-gs / tauI + GP2 * sumE + GP3 * sumI) * dt;
            ph2 = phase + (-GLI * c + C0F * one_c * inp
                           + ga * (C1F * one_c - s) + gb * (C2F * one_c - s)) * dt;
        }
        bool fired = active && (ph2 >= PIF);
        float spkv = fired ? 1.0f : 0.0f;
        if (fired) ph2 = ph2 - 2.0f * PIF;
        phase = ph2;

        if (active) {
            size_t o = (size_t)i * T_STEPS + t;
            gout[o]   = gs;
            spkout[o] = spkv;
            Vout[o]   = -58.5f + 3.5f * tanf(0.5f * ph2);
        }

        // -------- deterministic fired-list build (warp ballot compaction) ----
        unsigned bal = __ballot_sync(0xffffffffu, fired);
        if (lane == 0) sWcnt[w32] = __popc(bal);

        // deterministic Out partial: per-warp shuffle reduce of g*W
        float val = active ? gs * wv : 0.0f;
        #pragma unroll
        for (int off = 16; off > 0; off >>= 1)
            val += __shfl_down_sync(0xffffffffu, val, off);
        if (lane == 0) sRed[w32] = val;
        __syncthreads();

        int off = 0, cE = 0, cTt = 0;
        #pragma unroll
        for (int ww = 0; ww < NWARP; ww++) {
            int cw = sWcnt[ww];
            if (ww < w32) off += cw;
            cTt += cw;
            if ((b * NTHR + ww * 32) < NE) cE += cw;  // E/I boundary is warp-aligned
        }
        if (fired) {
            int pos = off + __popc(bal & ((1u << lane) - 1u));
            g_list[pnew][b * CAP + pos] = i;
        }
        if (tid == 0) {
            g_cntE[pnew][b] = cE;
            g_cntT[pnew][b] = cTt;
            g_outPart[b * T_STEPS + t] = ((sRed[0] + sRed[1]) + sRed[2]) + sRed[3];
        }

        // -------- grid barrier (sense via generation counter) ---------------
        __threadfence();
        __syncthreads();
        if (tid == 0) {
            unsigned target = (unsigned)t;
            if (atomicAdd(&g_barCnt, 1u) == NBLK - 1) {
                g_barCnt = 0;
                __threadfence();
                g_barGen = target;
            } else {
                while (g_barGen < target) { }
                __threadfence();
            }
        }
        __syncthreads();
    }
}

// ---------------- finalize: Out[t] = sum_b part[b][t] / N ----------------
__global__ void snn_finalize(float* Out) {
    int t = blockIdx.x * blockDim.x + threadIdx.x;
    if (t >= T_STEPS) return;
    float sm = 0.0f;
    if (t > 0) {
        #pragma unroll 1
        for (int b = 0; b < NBLK; b++)
            sm += g_outPart[b * T_STEPS + t];
    }
    Out[t] = sm / 5000.0f;
}

extern "C" void kernel_launch(void* const* d_in, const int* in_sizes, int n_in,
                              void* d_out, int out_size) {
    const float* dt    = (const float*)d_in[0];
    const float* Input = (const float*)d_in[1];
    const float* conn  = (const float*)d_in[2];
    const float* Wout  = (const float*)d_in[3];
    // d_in[4..7]: N_E, N_I, taud_E, taud_I — fixed by the problem, baked in as constants.

    float* out = (float*)d_out;
    float* Out  = out;                       // [T]
    float* Vout = out + T_STEPS;             // [N, T]
    float* gout = Vout + (size_t)N_TOT * T_STEPS;
    float* spkout = gout + (size_t)N_TOT * T_STEPS;

    dim3 tgrid((N_TOT + 31) / 32, (N_TOT + 31) / 32);
    snn_transpose<<<tgrid, dim3(32, 8)>>>(conn);
    snn_init<<<(N_TOT + 255) / 256, 256>>>(Vout, gout, spkout);
    snn_main<<<NBLK, NTHR>>>(dt, Input, Wout, Vout, gout, spkout);
    snn_finalize<<<(T_STEPS + 255) / 256, 256>>>(Out);
}

// round 3
// speedup vs baseline: 1.6119x; 1.6119x over previous
#include <cuda_runtime.h>
#include <math.h>

// Problem constants (fixed by setup_inputs)
#define N_TOT 5000
#define NE    4000
#define NI    1000
#define T_STEPS 1000
#define NBLK  40
#define NTHR  128
#define NWARP (NTHR/32)
#define CAP   128   // max fired per block = block size

// Model constants, matching the python reference (f32 roundings)
#define GLE 0.08f
#define GLI 0.1f
#define GP0 0.004069f
#define GP1 0.02672f
#define GP2 0.003276f
#define GP3 0.02138f
#define C0F ((float)(2.0/7.0))
#define C1F ((float)(117.0/7.0))
#define C2F ((float)(-23.0/7.0))
#define PIF 3.14159274101257324f   // float32(pi)

// ------- static device scratch (no allocations allowed) -------
__device__ float g_connT[(size_t)N_TOT * N_TOT];   // 100 MB: conn transposed
__device__ int   g_list[2][NBLK * CAP];            // double-buffered fired lists (per-block segments)
__device__ int   g_cntT[2][NBLK];
__device__ int   g_ready[NBLK];
__device__ float g_outPart[T_STEPS * NBLK];        // [t][b] partial sums of g*W

// ---------------- transpose conn -> connT (identical to R1) ----------------
__global__ void snn_transpose(const float* __restrict__ conn) {
    __shared__ float tile[32][33];
    int bx = blockIdx.x * 32, by = blockIdx.y * 32;
    int x = bx + threadIdx.x;
    #pragma unroll
    for (int r = threadIdx.y; r < 32; r += 8) {
        int y = by + r;
        if (x < N_TOT && y < N_TOT)
            tile[r][threadIdx.x] = conn[(size_t)y * N_TOT + x];
    }
    __syncthreads();
    int xo = by + threadIdx.x;
    #pragma unroll
    for (int r = threadIdx.y; r < 32; r += 8) {
        int yo = bx + r;
        if (xo < N_TOT && yo < N_TOT)
            g_connT[(size_t)yo * N_TOT + xo] = tile[threadIdx.x][r];  // connT[j][i] = conn[i][j]
    }
}

// ---------------- init: reset sync state + column 0 of outputs ----------------
__global__ void snn_init(float* Vout, float* gout, float* spkout) {
    int i = blockIdx.x * blockDim.x + threadIdx.x;
    if (i < NBLK) g_ready[i] = 0;
    if (i < 2 * NBLK) ((int*)g_cntT)[i] = 0;
    if (i < N_TOT) {
        size_t o = (size_t)i * T_STEPS;
        Vout[o]   = -58.5f;  // theta2V(0)
        gout[o]   = 0.0f;
        spkout[o] = 0.0f;
    }
}

// ---------------- main persistent simulation kernel ----------------
__global__ void __launch_bounds__(NTHR, 1) snn_main(
    const float* __restrict__ dtp,
    const float* __restrict__ Input,   // [N, T] row-major
    const float* __restrict__ Wout,    // [N]
    float* __restrict__ Vout,          // [N, T]
    float* __restrict__ gout,          // [N, T]
    float* __restrict__ spkout)        // [N, T]
{
    const int tid  = threadIdx.x;
    const int b    = blockIdx.x;
    const int i    = b * NTHR + tid;
    const bool active = (i < N_TOT);
    const bool isE    = (i < NE);
    const int  ii     = active ? i : 0;     // clamp for safe gather addressing
    const int  lane   = tid & 31;
    const int  w32    = tid >> 5;

    const float dt   = *dtp;
    const float tauE = 2.0f;
    const float tauI = 5.0f;

    float ga = 0.0f, gb = 0.0f, gs = 0.0f, phase = 0.0f;
    const float wv = active ? Wout[i] : 0.0f;
    const float* inrow = Input + (size_t)ii * T_STEPS;

    __shared__ int   sList[NBLK * CAP];   // flattened fired list (order-preserving)
    __shared__ int   sCnt[NBLK];
    __shared__ int   sOff[NBLK];
    __shared__ int   sF;
    __shared__ int   sWcnt[NWARP];
    __shared__ float sRed[NWARP];

    const float* cT = g_connT;

    for (int t = 1; t < T_STEPS; t++) {
        const int rb = (t - 1) & 1;   // read buffer (spikes from step t-1)
        const int wb = t & 1;         // write buffer (spikes from step t)

        // ---- distributed wait: all blocks must have published step t-1 ----
        if (tid < NBLK) {
            while (((volatile int*)g_ready)[tid] < t - 1) { }
        }
        __syncthreads();
        __threadfence();
        if (tid < NBLK) sCnt[tid] = __ldcg(&g_cntT[rb][tid]);
        __syncthreads();
        if (tid < NBLK) {
            int o = 0;
            for (int bb = 0; bb < tid; bb++) o += sCnt[bb];
            sOff[tid] = o;
            if (tid == NBLK - 1) sF = o + sCnt[tid];
        }
        __syncthreads();
        const int Ftot = sF;

        // hoist the (independent) input load to overlap its latency with staging
        const float inp = inrow[t];

        // ---- stage flattened fired list to smem (preserves global j order) ----
        for (int bb = w32; bb < NBLK; bb += NWARP) {
            int c = sCnt[bb], o = sOff[bb];
            const int* src = &g_list[rb][bb * CAP];
            for (int k = lane; k < c; k += 32) sList[o + k] = __ldcg(&src[k]);
        }
        __syncthreads();

        // ---- sparse gather: IDENTICAL accumulation order to R1 (ascending j) ----
        float sumE = 0.0f, sumI = 0.0f;
        #pragma unroll 8
        for (int m = 0; m < Ftot; m++) {
            int j = sList[m];
            float v = cT[(size_t)j * N_TOT + ii];
            if (j < NE) sumE += v; else sumI += v;   // same classification as R1's k<cE
        }

        // ---- pointwise neuron update (verbatim R1 expressions) ----
        float c = cosf(phase);
        float s = sinf(phase);
        float one_c = 1.0f + c;
        float ph2;
        if (isE) {
            ga = ga + (-ga / tauE + GP0 * sumE) * dt;
            gb = gb + (-gb / tauE + GP1 * sumI) * dt;
            gs = gs + (-gs / tauE + GP0 * sumE + GP1 * sumI) * dt;
            ph2 = phase + (-GLE * c + C0F * one_c * inp
                           + ga * (C1F * one_c - s) + gb * (C2F * one_c - s)) * dt;
        } else {
            ga = ga + (-ga / tauI + GP2 * sumE) * dt;
            gb = gb + (-gb / tauI + GP3 * sumI) * dt;
            gs = gs + (-gs / tauI + GP2 * sumE + GP3 * sumI) * dt;
            ph2 = phase + (-GLI * c + C0F * one_c * inp
                           + ga * (C1F * one_c - s) + gb * (C2F * one_c - s)) * dt;
        }
        bool fired = active && (ph2 >= PIF);
        float spkv = fired ? 1.0f : 0.0f;
        if (fired) ph2 = ph2 - 2.0f * PIF;
        phase = ph2;

        // ---- deterministic fired-list build (warp ballot compaction) ----
        unsigned bal = __ballot_sync(0xffffffffu, fired);
        if (lane == 0) sWcnt[w32] = __popc(bal);
        __syncthreads();

        int off = 0, cTt = 0;
        #pragma unroll
        for (int ww = 0; ww < NWARP; ww++) {
            int cw = sWcnt[ww];
            if (ww < w32) off += cw;
            cTt += cw;
        }
        if (fired) {
            int pos = off + __popc(bal & ((1u << lane) - 1u));
            g_list[wb][b * CAP + pos] = i;
        }
        if (tid == 0) g_cntT[wb][b] = cTt;

        // ---- publish step t ASAP, then do output stores off the critical path ----
        __threadfence();
        __syncthreads();
        if (tid == 0) ((volatile int*)g_ready)[b] = t;

        if (active) {
            size_t o = (size_t)i * T_STEPS + t;
            gout[o]   = gs;
            spkout[o] = spkv;
            Vout[o]   = -58.5f + 3.5f * tanf(0.5f * ph2);
        }

        // per-warp shuffle reduce of g*W -> per-block partial for Out
        float val = active ? gs * wv : 0.0f;
        #pragma unroll
        for (int o2 = 16; o2 > 0; o2 >>= 1)
            val += __shfl_down_sync(0xffffffffu, val, o2);
        if (lane == 0) sRed[w32] = val;
        __syncthreads();
        if (tid == 0)
            g_outPart[t * NBLK + b] = ((sRed[0] + sRed[1]) + sRed[2]) + sRed[3];
        // (sRed/sWcnt reuse is protected by the wait+syncthreads at loop top)
    }
}

// ---------------- finalize: Out[t] = sum_b part[t][b] / N ----------------
__global__ void snn_finalize(float* Out) {
    int t = blockIdx.x * blockDim.x + threadIdx.x;
    if (t >= T_STEPS) return;
    float sm = 0.0f;
    if (t > 0) {
        #pragma unroll
        for (int b = 0; b < NBLK; b++)
            sm += g_outPart[t * NBLK + b];
    }
    Out[t] = sm / 5000.0f;
}

extern "C" void kernel_launch(void* const* d_in, const int* in_sizes, int n_in,
                              void* d_out, int out_size) {
    const float* dt    = (const float*)d_in[0];
    const float* Input = (const float*)d_in[1];
    const float* conn  = (const float*)d_in[2];
    const float* Wout  = (const float*)d_in[3];

    float* out = (float*)d_out;
    float* Out  = out;                       // [T]
    float* Vout = out + T_STEPS;             // [N, T]
    float* gout = Vout + (size_t)N_TOT * T_STEPS;
    float* spkout = gout + (size_t)N_TOT * T_STEPS;

    dim3 tgrid((N_TOT + 31) / 32, (N_TOT + 31) / 32);
    snn_transpose<<<tgrid, dim3(32, 8)>>>(conn);
    snn_init<<<(N_TOT + 255) / 256, 256>>>(Vout, gout, spkout);
    snn_main<<<NBLK, NTHR>>>(dt, Input, Wout, Vout, gout, spkout);
    snn_finalize<<<(T_STEPS + 255) / 256, 256>>>(Out);
}

// round 4
// speedup vs baseline: 2.4825x; 1.5401x over previous
#include <cuda_runtime.h>
#include <math.h>

// Problem constants (fixed by setup_inputs)
#define N_TOT 5000
#define NE    4000
#define NI    1000
#define T_STEPS 1000
#define NBLK  40
#define NTHR  128
#define NWARP (NTHR/32)
#define CAP   128   // max fired per block = block size

// Model constants, matching the python reference (f32 roundings)
#define GLE 0.08f
#define GLI 0.1f
#define GP0 0.004069f
#define GP1 0.02672f
#define GP2 0.003276f
#define GP3 0.02138f
#define C0F ((float)(2.0/7.0))
#define C1F ((float)(117.0/7.0))
#define C2F ((float)(-23.0/7.0))
#define PIF 3.14159274101257324f   // float32(pi)

// ------- static device scratch (no allocations allowed) -------
__device__ float g_connT[(size_t)N_TOT * N_TOT];   // 100 MB: conn transposed
__device__ int   g_list[2][NBLK * CAP];            // double-buffered fired lists (per-block segments)
__device__ int   g_flag[2][NBLK];                  // packed: t*256 + cnt
__device__ float g_gcol[(size_t)T_STEPS * N_TOT];  // coalesced g staging [t][N] for Out

__device__ __forceinline__ int ld_acquire_gpu(const int* p) {
    int v;
    asm volatile("ld.acquire.gpu.b32 %0, [%1];" : "=r"(v) : "l"(p) : "memory");
    return v;
}
__device__ __forceinline__ void st_relaxed_gpu(int* p, int v) {
    asm volatile("st.relaxed.gpu.b32 [%0], %1;" :: "l"(p), "r"(v) : "memory");
}

// ---------------- tiny no-op kernels: shift ncu's -s 5 window onto snn_main ----
__global__ void snn_dummy() {}

// ---------------- transpose conn -> connT ----------------
__global__ void snn_transpose(const float* __restrict__ conn) {
    __shared__ float tile[32][33];
    int bx = blockIdx.x * 32, by = blockIdx.y * 32;
    int x = bx + threadIdx.x;
    #pragma unroll
    for (int r = threadIdx.y; r < 32; r += 8) {
        int y = by + r;
        if (x < N_TOT && y < N_TOT)
            tile[r][threadIdx.x] = conn[(size_t)y * N_TOT + x];
    }
    __syncthreads();
    int xo = by + threadIdx.x;
    #pragma unroll
    for (int r = threadIdx.y; r < 32; r += 8) {
        int yo = bx + r;
        if (xo < N_TOT && yo < N_TOT)
            g_connT[(size_t)yo * N_TOT + xo] = tile[threadIdx.x][r];  // connT[j][i] = conn[i][j]
    }
}

// ---------------- init: reset sync state + column 0 of outputs ----------------
__global__ void snn_init(float* Vout, float* gout, float* spkout) {
    int i = blockIdx.x * blockDim.x + threadIdx.x;
    if (i < 2 * NBLK) ((int*)g_flag)[i] = 0;   // step 0, cnt 0
    if (i < N_TOT) {
        size_t o = (size_t)i * T_STEPS;
        Vout[o]   = -58.5f;  // theta2V(0)
        gout[o]   = 0.0f;
        spkout[o] = 0.0f;
    }
}

// ---------------- main persistent simulation kernel ----------------
__global__ void __launch_bounds__(NTHR, 1) snn_main(
    const float* __restrict__ dtp,
    const float* __restrict__ Input,   // [N, T] row-major
    float* __restrict__ Vout,          // [N, T]
    float* __restrict__ gout,          // [N, T]
    float* __restrict__ spkout)        // [N, T]
{
    const int tid  = threadIdx.x;
    const int b    = blockIdx.x;
    const int i    = b * NTHR + tid;
    const bool active = (i < N_TOT);
    const bool isE    = (i < NE);
    const int  ii     = active ? i : 0;     // clamp for safe gather addressing
    const int  lane   = tid & 31;
    const int  w32    = tid >> 5;

    const float dt   = *dtp;
    const float tauE = 2.0f;
    const float tauI = 5.0f;

    float ga = 0.0f, gb = 0.0f, gs = 0.0f, phase = 0.0f;
    const float* inrow = Input + (size_t)ii * T_STEPS;

    __shared__ int sList[NBLK * CAP];   // flattened fired list (order-preserving)
    __shared__ int sCnt[NBLK];
    __shared__ int sOff[NBLK];
    __shared__ int sF;
    __shared__ int sWcnt[NWARP];

    const float* cT = g_connT;

    float inp = inrow[1];   // prefetched input for the current step

    for (int t = 1; t < T_STEPS; t++) {
        const int rb = (t - 1) & 1;   // read buffer (spikes from step t-1)
        const int wb = t & 1;         // write buffer (spikes from step t)

        // ---- distributed wait; flag carries the spike count (saves one L2 RT) ----
        if (tid < NBLK) {
            int v;
            do { v = ld_acquire_gpu(&g_flag[rb][tid]); } while ((v >> 8) < t - 1);
            sCnt[tid] = v & 255;
        }
        __syncthreads();
        if (tid < NBLK) {
            int o = 0;
            for (int bb = 0; bb < tid; bb++) o += sCnt[bb];
            sOff[tid] = o;
            if (tid == NBLK - 1) sF = o + sCnt[tid];
        }
        __syncthreads();
        const int Ftot = sF;

        // ---- prefetch next step's input early (hide DRAM latency) ----
        float inp_next = 0.0f;
        if (t + 1 < T_STEPS) inp_next = inrow[t + 1];

        // ---- sparse gather (skipped entirely in the common F==0 case) ----
        float sumE = 0.0f, sumI = 0.0f;
        if (Ftot > 0) {
            // stage flattened fired list to smem (preserves global j order)
            for (int bb = w32; bb < NBLK; bb += NWARP) {
                int c = sCnt[bb], o = sOff[bb];
                const int* src = &g_list[rb][bb * CAP];
                for (int k = lane; k < c; k += 32) sList[o + k] = __ldcg(&src[k]);
            }
            __syncthreads();
            #pragma unroll 16
            for (int m = 0; m < Ftot; m++) {
                int j = sList[m];
                float v = cT[(size_t)j * N_TOT + ii];
                if (j < NE) sumE += v; else sumI += v;   // ascending-j order, same as R3
            }
        }

        // ---- pointwise neuron update (verbatim R3 expressions) ----
        float c = cosf(phase);
        float s = sinf(phase);
        float one_c = 1.0f + c;
        float ph2;
        if (isE) {
            ga = ga + (-ga / tauE + GP0 * sumE) * dt;
            gb = gb + (-gb / tauE + GP1 * sumI) * dt;
            gs = gs + (-gs / tauE + GP0 * sumE + GP1 * sumI) * dt;
            ph2 = phase + (-GLE * c + C0F * one_c * inp
                           + ga * (C1F * one_c - s) + gb * (C2F * one_c - s)) * dt;
        } else {
            ga = ga + (-ga / tauI + GP2 * sumE) * dt;
            gb = gb + (-gb / tauI + GP3 * sumI) * dt;
            gs = gs + (-gs / tauI + GP2 * sumE + GP3 * sumI) * dt;
            ph2 = phase + (-GLI * c + C0F * one_c * inp
                           + ga * (C1F * one_c - s) + gb * (C2F * one_c - s)) * dt;
        }
        bool fired = active && (ph2 >= PIF);
        float spkv = fired ? 1.0f : 0.0f;
        if (fired) ph2 = ph2 - 2.0f * PIF;
        phase = ph2;
        inp = inp_next;

        // ---- deterministic fired-list build (warp ballot compaction) ----
        unsigned bal = __ballot_sync(0xffffffffu, fired);
        if (lane == 0) sWcnt[w32] = __popc(bal);
        __syncthreads();

        int off = 0, cTt = 0;
        #pragma unroll
        for (int ww = 0; ww < NWARP; ww++) {
            int cw = sWcnt[ww];
            if (ww < w32) off += cw;
            cTt += cw;
        }
        if (fired) {
            int pos = off + __popc(bal & ((1u << lane) - 1u));
            g_list[wb][b * CAP + pos] = i;
        }

        // ---- publish step t (count packed in flag), then tail stores ----
        __threadfence();
        __syncthreads();
        if (tid == 0) st_relaxed_gpu(&g_flag[wb][b], t * 256 + cTt);

        if (active) {
            g_gcol[(size_t)t * N_TOT + i] = gs;     // coalesced, for Out finalize
            size_t o = (size_t)i * T_STEPS + t;
            gout[o]   = gs;
            spkout[o] = spkv;
            Vout[o]   = -58.5f + 3.5f * tanf(0.5f * ph2);
        }
        // smem reuse (sCnt/sWcnt/sList) is protected by the wait + syncthreads at loop top
    }
}

// ---------------- finalize: Out[t] = (g_gcol[t] . W) / N ----------------
__global__ void snn_finalize(const float* __restrict__ W, float* __restrict__ Out) {
    const int t = blockIdx.x;
    const int tid = threadIdx.x;
    __shared__ float sred[8];
    float acc = 0.0f;
    if (t > 0) {
        const float* gr = &g_gcol[(size_t)t * N_TOT];
        for (int n = tid; n < N_TOT; n += 256) acc += gr[n] * W[n];
    }
    #pragma unroll
    for (int off = 16; off > 0; off >>= 1) acc += __shfl_down_sync(0xffffffffu, acc, off);
    if ((tid & 31) == 0) sred[tid >> 5] = acc;
    __syncthreads();
    if (tid == 0) {
        float sm = 0.0f;
        #pragma unroll
        for (int ww = 0; ww < 8; ww++) sm += sred[ww];
        Out[t] = sm / 5000.0f;
    }
}

extern "C" void kernel_launch(void* const* d_in, const int* in_sizes, int n_in,
                              void* d_out, int out_size) {
    const float* dt    = (const float*)d_in[0];
    const float* Input = (const float*)d_in[1];
    const float* conn  = (const float*)d_in[2];
    const float* Wout  = (const float*)d_in[3];

    float* out = (float*)d_out;
    float* Out  = out;                       // [T]
    float* Vout = out + T_STEPS;             // [N, T]
    float* gout = Vout + (size_t)N_TOT * T_STEPS;
    float* spkout = gout + (size_t)N_TOT * T_STEPS;

    // 3 dummies so ncu (-s 5 -c 1) profiles snn_main (launch #6)
    snn_dummy<<<1, 1>>>();
    snn_dummy<<<1, 1>>>();
    snn_dummy<<<1, 1>>>();

    dim3 tgrid((N_TOT + 31) / 32, (N_TOT + 31) / 32);
    snn_transpose<<<tgrid, dim3(32, 8)>>>(conn);
    snn_init<<<(N_TOT + 255) / 256, 256>>>(Vout, gout, spkout);
    snn_main<<<NBLK, NTHR>>>(dt, Input, Vout, gout, spkout);
    snn_finalize<<<T_STEPS, 256>>>(Wout, Out);
}

// round 5
// speedup vs baseline: 3.2253x; 1.2992x over previous
#include <cuda_runtime.h>
#include <math.h>

// Problem constants (fixed by setup_inputs)
#define N_TOT 5000
#define NE    4000
#define NI    1000
#define T_STEPS 1000
#define NBLK  20
#define NTHR  256
#define NWARP (NTHR/32)
#define CAP   256   // max fired per block = block size
#define WTOT  (NBLK * NWARP)   // 160 warps total

// Model constants, matching the python reference (f32 roundings)
#define GLE 0.08f
#define GLI 0.1f
#define GP0 0.004069f
#define GP1 0.02672f
#define GP2 0.003276f
#define GP3 0.02138f
#define C0F ((float)(2.0/7.0))
#define C1F ((float)(117.0/7.0))
#define C2F ((float)(-23.0/7.0))
#define PIF 3.14159274101257324f   // float32(pi)

// ------- static device scratch (no allocations allowed) -------
__device__ float g_connT[(size_t)N_TOT * N_TOT];     // 100 MB: conn transposed
__device__ int   g_list[2][NBLK * CAP];              // double-buffered fired lists
__device__ int   g_flag[2][NBLK];                    // packed: t*512 + cnt
__device__ float g_gcol [(size_t)T_STEPS * N_TOT];   // g staged [t][N]
__device__ float g_phcol[(size_t)T_STEPS * N_TOT];   // phase staged [t][N]
__device__ unsigned g_spbits[(size_t)T_STEPS * WTOT];// spike ballot bits [t][warp]

__device__ __forceinline__ int ld_acquire_gpu(const int* p) {
    int v;
    asm volatile("ld.acquire.gpu.b32 %0, [%1];" : "=r"(v) : "l"(p) : "memory");
    return v;
}
__device__ __forceinline__ void st_relaxed_gpu(int* p, int v) {
    asm volatile("st.relaxed.gpu.b32 [%0], %1;" :: "l"(p), "r"(v) : "memory");
}

// ---------------- tiny no-op kernels: shift ncu's profiled slot onto snn_main ----
__global__ void snn_dummy() {}

// ---------------- transpose conn -> connT ----------------
__global__ void snn_transpose(const float* __restrict__ conn) {
    __shared__ float tile[32][33];
    int bx = blockIdx.x * 32, by = blockIdx.y * 32;
    int x = bx + threadIdx.x;
    #pragma unroll
    for (int r = threadIdx.y; r < 32; r += 8) {
        int y = by + r;
        if (x < N_TOT && y < N_TOT)
            tile[r][threadIdx.x] = conn[(size_t)y * N_TOT + x];
    }
    __syncthreads();
    int xo = by + threadIdx.x;
    #pragma unroll
    for (int r = threadIdx.y; r < 32; r += 8) {
        int yo = bx + r;
        if (xo < N_TOT && yo < N_TOT)
            g_connT[(size_t)yo * N_TOT + xo] = tile[threadIdx.x][r];  // connT[j][i] = conn[i][j]
    }
}

// ---------------- init: reset sync state + t=0 staged rows ----------------
__global__ void snn_init() {
    int i = blockIdx.x * blockDim.x + threadIdx.x;
    if (i < 2 * NBLK) ((int*)g_flag)[i] = 0;   // step 0, cnt 0
    if (i < WTOT) g_spbits[i] = 0u;            // t=0 spike bits
    if (i < N_TOT) {
        g_gcol[i]  = 0.0f;                     // t=0 rows
        g_phcol[i] = 0.0f;
    }
}

// ---------------- main persistent simulation kernel ----------------
__global__ void __launch_bounds__(NTHR, 1) snn_main(
    const float* __restrict__ dtp,
    const float* __restrict__ Input)   // [N, T] row-major
{
    const int tid  = threadIdx.x;
    const int b    = blockIdx.x;
    const int i    = b * NTHR + tid;
    const bool active = (i < N_TOT);
    const bool isE    = (i < NE);
    const int  ii     = active ? i : 0;     // clamp for safe gather addressing
    const int  lane   = tid & 31;
    const int  w32    = tid >> 5;

    const float dt   = *dtp;
    const float tauE = 2.0f;
    const float tauI = 5.0f;

    float ga = 0.0f, gb = 0.0f, gs = 0.0f, phase = 0.0f;
    const float* inrow = Input + (size_t)ii * T_STEPS;

    __shared__ int sList[NBLK * CAP];   // flattened fired list (order-preserving)
    __shared__ int sCnt[NBLK];
    __shared__ int sOff[NBLK];
    __shared__ int sF;
    __shared__ int sWcnt[NWARP];

    const float* cT = g_connT;

    float inp = inrow[1];   // prefetched input for the current step

    for (int t = 1; t < T_STEPS; t++) {
        const int rb = (t - 1) & 1;   // read buffer (spikes from step t-1)
        const int wb = t & 1;         // write buffer (spikes from step t)

        // ---- distributed wait; flag carries the spike count ----
        int cnt = 0;
        if (tid < NBLK) {
            int v;
            do { v = ld_acquire_gpu(&g_flag[rb][tid]); } while ((v >> 9) < t - 1);
            cnt = v & 511;
            sCnt[tid] = cnt;
        }
        if (tid < 32) {   // warp-0 shuffle reduce -> Ftot (lanes >= NBLK hold 0)
            #pragma unroll
            for (int o = 16; o > 0; o >>= 1)
                cnt += __shfl_down_sync(0xffffffffu, cnt, o);
            if (tid == 0) sF = cnt;
        }
        __syncthreads();                // B1
        const int Ftot = sF;

        // ---- prefetch next step's input early (hide DRAM latency) ----
        float inp_next = 0.0f;
        if (t + 1 < T_STEPS) inp_next = inrow[t + 1];

        // ---- sparse gather (skipped entirely in the common F==0 case) ----
        float sumE = 0.0f, sumI = 0.0f;
        if (Ftot > 0) {
            if (tid < NBLK) {           // serial prefix only on the rare path
                int o = 0;
                for (int bb = 0; bb < tid; bb++) o += sCnt[bb];
                sOff[tid] = o;
            }
            __syncthreads();
            for (int bb = w32; bb < NBLK; bb += NWARP) {
                int c = sCnt[bb], o = sOff[bb];
                const int* src = &g_list[rb][bb * CAP];
                for (int k = lane; k < c; k += 32) sList[o + k] = __ldcg(&src[k]);
            }
            __syncthreads();
            #pragma unroll 16
            for (int m = 0; m < Ftot; m++) {
                int j = sList[m];
                float v = cT[(size_t)j * N_TOT + ii];
                if (j < NE) sumE += v; else sumI += v;   // ascending-j order (bit-identical)
            }
        }

        // ---- pointwise neuron update (verbatim R3/R4 expressions) ----
        float c = cosf(phase);
        float s = sinf(phase);
        float one_c = 1.0f + c;
        float ph2;
        if (isE) {
            ga = ga + (-ga / tauE + GP0 * sumE) * dt;
            gb = gb + (-gb / tauE + GP1 * sumI) * dt;
            gs = gs + (-gs / tauE + GP0 * sumE + GP1 * sumI) * dt;
            ph2 = phase + (-GLE * c + C0F * one_c * inp
                           + ga * (C1F * one_c - s) + gb * (C2F * one_c - s)) * dt;
        } else {
            ga = ga + (-ga / tauI + GP2 * sumE) * dt;
            gb = gb + (-gb / tauI + GP3 * sumI) * dt;
            gs = gs + (-gs / tauI + GP2 * sumE + GP3 * sumI) * dt;
            ph2 = phase + (-GLI * c + C0F * one_c * inp
                           + ga * (C1F * one_c - s) + gb * (C2F * one_c - s)) * dt;
        }
        bool fired = active && (ph2 >= PIF);
        if (fired) ph2 = ph2 - 2.0f * PIF;
        phase = ph2;
        inp = inp_next;

        // ---- deterministic fired-list build (warp ballot compaction) ----
        unsigned bal = __ballot_sync(0xffffffffu, fired);
        if (lane == 0) sWcnt[w32] = __popc(bal);
        __syncthreads();                // B2

        int off = 0, cTt = 0;
        #pragma unroll
        for (int ww = 0; ww < NWARP; ww++) {
            int cw = sWcnt[ww];
            if (ww < w32) off += cw;
            cTt += cw;
        }
        if (fired) {
            int pos = off + __popc(bal & ((1u << lane) - 1u));
            g_list[wb][b * CAP + pos] = i;
        }
        if (cTt > 0) {                  // block-uniform branch
            if (fired) __threadfence(); // order list writes before the flag
            __syncthreads();
        }
        if (tid == 0) st_relaxed_gpu(&g_flag[wb][b], t * 512 + cTt);

        // ---- coalesced tail stores (independent of other blocks) ----
        if (active) {
            size_t o = (size_t)t * N_TOT + i;
            g_gcol[o]  = gs;
            g_phcol[o] = ph2;
        }
        if (lane == 0) g_spbits[(size_t)t * WTOT + b * NWARP + w32] = bal;
        // smem reuse is protected by the wait + B1 at loop top
    }
}

// ---------------- post: [t][N] staging -> [N][T] outputs, V = theta2V ----------
__global__ void snn_post(float* __restrict__ Vout, float* __restrict__ gout,
                         float* __restrict__ spkout) {
    __shared__ float tp[32][33], tg[32][33], ts[32][33];
    int t0 = blockIdx.x * 32, n0 = blockIdx.y * 32;
    int n = n0 + threadIdx.x;
    #pragma unroll
    for (int ty = threadIdx.y; ty < 32; ty += 8) {
        int t = t0 + ty;
        if (t < T_STEPS && n < N_TOT) {
            size_t o = (size_t)t * N_TOT + n;
            tp[ty][threadIdx.x] = g_phcol[o];
            tg[ty][threadIdx.x] = g_gcol[o];
            unsigned bits = g_spbits[(size_t)t * WTOT + (n >> 5)];
            ts[ty][threadIdx.x] = ((bits >> (n & 31)) & 1u) ? 1.0f : 0.0f;
        }
    }
    __syncthreads();
    int t = t0 + threadIdx.x;
    #pragma unroll
    for (int ny = threadIdx.y; ny < 32; ny += 8) {
        int nn = n0 + ny;
        if (t < T_STEPS && nn < N_TOT) {
            size_t o = (size_t)nn * T_STEPS + t;
            Vout[o]   = -58.5f + 3.5f * tanf(0.5f * tp[threadIdx.x][ny]);
            gout[o]   = tg[threadIdx.x][ny];
            spkout[o] = ts[threadIdx.x][ny];
        }
    }
}

// ---------------- finalize: Out[t] = (g_gcol[t] . W) / N ----------------
__global__ void snn_finalize(const float* __restrict__ W, float* __restrict__ Out) {
    const int t = blockIdx.x;
    const int tid = threadIdx.x;
    __shared__ float sred[8];
    float acc = 0.0f;
    if (t > 0) {
        const float* gr = &g_gcol[(size_t)t * N_TOT];
        for (int n = tid; n < N_TOT; n += 256) acc += gr[n] * W[n];
    }
    #pragma unroll
    for (int off = 16; off > 0; off >>= 1) acc += __shfl_down_sync(0xffffffffu, acc, off);
    if ((tid & 31) == 0) sred[tid >> 5] = acc;
    __syncthreads();
    if (tid == 0) {
        float sm = 0.0f;
        #pragma unroll
        for (int ww = 0; ww < 8; ww++) sm += sred[ww];
        Out[t] = sm / 5000.0f;
    }
}

extern "C" void kernel_launch(void* const* d_in, const int* in_sizes, int n_in,
                              void* d_out, int out_size) {
    const float* dt    = (const float*)d_in[0];
    const float* Input = (const float*)d_in[1];
    const float* conn  = (const float*)d_in[2];
    const float* Wout  = (const float*)d_in[3];

    float* out = (float*)d_out;
    float* Out  = out;                       // [T]
    float* Vout = out + T_STEPS;             // [N, T]
    float* gout = Vout + (size_t)N_TOT * T_STEPS;
    float* spkout = gout + (size_t)N_TOT * T_STEPS;

    // 5 dummies so ncu's profiled slot lands on snn_main
    snn_dummy<<<1, 1>>>();
    snn_dummy<<<1, 1>>>();
    snn_dummy<<<1, 1>>>();
    snn_dummy<<<1, 1>>>();
    snn_dummy<<<1, 1>>>();

    dim3 tgrid((N_TOT + 31) / 32, (N_TOT + 31) / 32);
    snn_transpose<<<tgrid, dim3(32, 8)>>>(conn);
    snn_init<<<(N_TOT + 255) / 256, 256>>>();
    snn_main<<<NBLK, NTHR>>>(dt, Input);
    {
        dim3 g((T_STEPS + 31) / 32, (N_TOT + 31) / 32);
        snn_post<<<g, dim3(32, 8)>>>(Vout, gout, spkout);
    }
    snn_finalize<<<T_STEPS, 256>>>(Wout, Out);
}